// round 10
// baseline (speedup 1.0000x reference)
#include <cuda_runtime.h>

// Blur_80281528697499: depthwise UpFirDn2D(up=2, dn=2, 4x4) == 2x2 stencil
// with odd-odd filter taps. x:(8,256,128,128) f32 -> out same shape.
//
// R=4 row-strip (best measured per-warp structure: 5 independent LDG.128,
// 32 regs) with 512-thread CTAs: 16 warps/CTA, 4 CTAs/SM -> 64 warps/SM
// (100% occupancy) and a small grid (4096 = 2 blocks/plane) with minimal
// fractional-wave residue. Goal: more resident warps -> more outstanding
// DRAM requests -> fewer DRAM idle cycles (was 76.5% busy).

#define NB 8
#define NC 256
#define NH 128
#define NW 128
#define R  4   // output rows per warp

__global__ void __launch_bounds__(512) blur2x2_strip_kernel(
    const float* __restrict__ x,
    const float* __restrict__ filt,
    float* __restrict__ out)
{
    const int pblk  = blockIdx.x & 1;          // 2 blocks per plane
    const int plane = blockIdx.x >> 1;         // b*C + c, 0..2047
    const int c     = plane & (NC - 1);

    const int warp  = threadIdx.x >> 5;        // 0..15
    const int lane  = threadIdx.x & 31;
    const int y0    = pblk * 64 + warp * R;    // first output row of strip

    const float4* base = reinterpret_cast<const float4*>(
        x + (size_t)plane * (NH * NW));

    // Front-load R+1 = 5 rows (independent -> 5 LDG.128 in flight).
    float4 r[R + 1];
    const bool last_strip = (y0 + R >= NH);    // warp-uniform
    #pragma unroll
    for (int i = 0; i < R; i++)
        r[i] = base[(y0 + i) * (NW / 4) + lane];
    if (!last_strip)
        r[R] = base[(y0 + R) * (NW / 4) + lane];
    else
        r[R] = make_float4(0.0f, 0.0f, 0.0f, 0.0f);

    // Per-channel filter taps (only odd-odd taps of the 4x4 contribute).
    const float* fp = filt + c * 16;
    const float wA = __ldg(fp + 5);    // f[1][1]
    const float wB = __ldg(fp + 7);    // f[1][3]
    const float wC = __ldg(fp + 13);   // f[3][1]
    const float wD = __ldg(fp + 15);   // f[3][3]

    // Next-lane .x for each row (right neighbor of the .w element).
    float n[R + 1];
    #pragma unroll
    for (int i = 0; i < R + 1; i++) {
        n[i] = __shfl_down_sync(0xffffffffu, r[i].x, 1);
        if (lane == 31) n[i] = 0.0f;           // right boundary -> 0
    }

    float4* obase = reinterpret_cast<float4*>(out) +
                    (size_t)plane * (NH * NW / 4) + lane;

    #pragma unroll
    for (int i = 0; i < R; i++) {
        const float4 a = r[i];
        const float4 b = r[i + 1];
        float4 o;
        o.x = wA * a.x + wB * a.y + wC * b.x + wD * b.y;
        o.y = wA * a.y + wB * a.z + wC * b.y + wD * b.z;
        o.z = wA * a.z + wB * a.w + wC * b.z + wD * b.w;
        o.w = wA * a.w + wB * n[i] + wC * b.w + wD * n[i + 1];
        obase[(y0 + i) * (NW / 4)] = o;
    }
}

extern "C" void kernel_launch(void* const* d_in, const int* in_sizes, int n_in,
                              void* d_out, int out_size)
{
    const float* x    = (const float*)d_in[0];   // (8,256,128,128) f32
    const float* filt = (const float*)d_in[1];   // (256,1,4,4) f32
    float* out = (float*)d_out;                  // (8,256,128,128) f32

    const int planes = NB * NC;                  // 2048
    const int blocks = planes * 2;               // 4096
    blur2x2_strip_kernel<<<blocks, 512>>>(x, filt, out);
}